// round 1
// baseline (speedup 1.0000x reference)
#include <cuda_runtime.h>
#include <math.h>

// Problem dims (fixed by the dataset)
#define NPTS 8192
#define DDIM 2048
#define HDIM 2048
#define ODIM 128
#define KNNK 10
#define NEDGE (NPTS * KNNK)

// ---------------------------------------------------------------------------
// Scratch (static __device__ globals -- allocation-free per harness rules)
// ---------------------------------------------------------------------------
__device__ float g_f[NPTS * DDIM];        // normalized features
__device__ float g_sq[NPTS];              // row squared norms of f
__device__ float g_d2[NPTS * NPTS];       // pairwise squared distances (256MB)
__device__ int   g_knn[NEDGE];            // 10 nearest (excl self) per row
__device__ int   g_cnt[NPTS];             // incoming edge counts
__device__ float g_dinv[NPTS];            // deg^{-1/2} (deg = incoming + 1)
__device__ int   g_off[NPTS + 1];         // CSR offsets (incoming)
__device__ int   g_fill[NPTS];            // CSR fill cursors
__device__ int   g_csr[NEDGE];            // CSR incoming source lists
__device__ float g_h[NPTS * HDIM];        // GEMM out (pre-aggregation)
__device__ float g_a[NPTS * HDIM];        // aggregated + BN + ReLU
__device__ float g_x[NPTS * DDIM];        // x1 / x3 buffer
__device__ float g_x2[NPTS * DDIM];       // x2 buffer
__device__ float g_h3[NPTS * ODIM];
__device__ float g_a3[NPTS * ODIM];

// ---------------------------------------------------------------------------
// Row L2-normalize; optionally also write row squared-norm of the result
// ---------------------------------------------------------------------------
__global__ __launch_bounds__(256)
void normalize_kernel(const float* __restrict__ x, float* __restrict__ f,
                      float* __restrict__ sq, int cols)
{
    int row = blockIdx.x;
    const float4* xr = (const float4*)(x + (size_t)row * cols);
    float4* fr = (float4*)(f + (size_t)row * cols);
    int n4 = cols >> 2;

    float s = 0.f;
    for (int i = threadIdx.x; i < n4; i += 256) {
        float4 v = xr[i];
        s += v.x * v.x + v.y * v.y + v.z * v.z + v.w * v.w;
    }
    __shared__ float red[256];
    red[threadIdx.x] = s;
    __syncthreads();
    for (int st = 128; st > 0; st >>= 1) {
        if (threadIdx.x < st) red[threadIdx.x] += red[threadIdx.x + st];
        __syncthreads();
    }
    __shared__ float inv_s;
    if (threadIdx.x == 0) {
        float ss = red[0];
        float nrm = sqrtf(ss);
        float inv = 1.0f / fmaxf(nrm, 1e-12f);
        inv_s = inv;
        if (sq) sq[row] = ss * inv * inv;
    }
    __syncthreads();
    float inv = inv_s;
    for (int i = threadIdx.x; i < n4; i += 256) {
        float4 v = xr[i];
        v.x *= inv; v.y *= inv; v.z *= inv; v.w *= inv;
        fr[i] = v;
    }
}

// ---------------------------------------------------------------------------
// Tiled fp32 GEMM. C[M,N] = A[M,K] @ B  (B is [K,N] row-major, or [N,K]
// row-major when TRANSB, i.e. C = A @ B^T).
// Epilogue modes:
//   0 PLAIN    : C = acc
//   1 BIASADD  : C = acc + bias[col] + E[row,col]
//   2 D2       : C = sq[row] + sq[col] - 2*acc
// ---------------------------------------------------------------------------
#define BM 128
#define BN 128
#define BK 16
#define TM 8
#define TN 8

template<int MODE, bool TRANSB>
__global__ __launch_bounds__(256, 2)
void gemm_kernel(const float* __restrict__ A, const float* __restrict__ B,
                 float* __restrict__ C, int M, int Nn, int K,
                 const float* __restrict__ bias, const float* __restrict__ E,
                 const float* __restrict__ sqv)
{
    __shared__ float As[BK][BM + 4];
    __shared__ float Bs[BK][BN + 4];

    int tid = threadIdx.x;
    int tx = tid & 15;        // 0..15 -> column group
    int ty = tid >> 4;        // 0..15 -> row group
    int rowBase = blockIdx.y * BM;
    int colBase = blockIdx.x * BN;

    float acc[TM][TN];
#pragma unroll
    for (int m = 0; m < TM; ++m)
#pragma unroll
        for (int n = 0; n < TN; ++n) acc[m][n] = 0.f;

    for (int kt = 0; kt < K; kt += BK) {
        // Load A tile: 128 rows x 16 cols, transposed into As[k][m]
#pragma unroll
        for (int l = 0; l < 2; ++l) {
            int idx = tid + l * 256;
            int r  = idx >> 2;
            int c4 = (idx & 3) * 4;
            float4 v = *(const float4*)&A[(size_t)(rowBase + r) * K + kt + c4];
            As[c4 + 0][r] = v.x; As[c4 + 1][r] = v.y;
            As[c4 + 2][r] = v.z; As[c4 + 3][r] = v.w;
        }
        if (TRANSB) {
            // B is [N,K]: load 128 rows(j) x 16 cols(k), transpose into Bs[k][j]
#pragma unroll
            for (int l = 0; l < 2; ++l) {
                int idx = tid + l * 256;
                int r  = idx >> 2;
                int c4 = (idx & 3) * 4;
                float4 v = *(const float4*)&B[(size_t)(colBase + r) * K + kt + c4];
                Bs[c4 + 0][r] = v.x; Bs[c4 + 1][r] = v.y;
                Bs[c4 + 2][r] = v.z; Bs[c4 + 3][r] = v.w;
            }
        } else {
            // B is [K,N]: 16 rows x 128 cols, direct
#pragma unroll
            for (int l = 0; l < 2; ++l) {
                int idx = tid + l * 256;
                int r  = idx >> 5;
                int c4 = (idx & 31) * 4;
                float4 v = *(const float4*)&B[(size_t)(kt + r) * Nn + colBase + c4];
                *(float4*)&Bs[r][c4] = v;
            }
        }
        __syncthreads();

#pragma unroll
        for (int kk = 0; kk < BK; ++kk) {
            float ra[TM], rb[TN];
#pragma unroll
            for (int m = 0; m < TM; ++m) ra[m] = As[kk][ty * TM + m];
#pragma unroll
            for (int n = 0; n < TN; ++n) rb[n] = Bs[kk][tx * TN + n];
#pragma unroll
            for (int m = 0; m < TM; ++m)
#pragma unroll
                for (int n = 0; n < TN; ++n)
                    acc[m][n] += ra[m] * rb[n];
        }
        __syncthreads();
    }

    int r0 = rowBase + ty * TM;
    int c0 = colBase + tx * TN;
#pragma unroll
    for (int m = 0; m < TM; ++m) {
        int r = r0 + m;
        float sr = (MODE == 2) ? sqv[r] : 0.f;
#pragma unroll
        for (int n4 = 0; n4 < TN; n4 += 4) {
            float4 o;
            float* po = &o.x;
#pragma unroll
            for (int j = 0; j < 4; ++j) {
                int c = c0 + n4 + j;
                float v = acc[m][n4 + j];
                if (MODE == 2) {
                    po[j] = sr + sqv[c] - 2.0f * v;
                } else if (MODE == 1) {
                    po[j] = v + bias[c] + E[(size_t)r * Nn + c];
                } else {
                    po[j] = v;
                }
            }
            *(float4*)&C[(size_t)r * Nn + c0 + n4] = o;
        }
    }
}

// ---------------------------------------------------------------------------
// Top-10 smallest (excluding self) per row of d2, one warp per row.
// Ties broken by smaller index (matches jax.lax.top_k stability).
// ---------------------------------------------------------------------------
__device__ __forceinline__ bool lessp(float v1, int i1, float v2, int i2)
{
    return (v1 < v2) || (v1 == v2 && i1 < i2);
}

__global__ __launch_bounds__(256)
void topk_kernel(const float* __restrict__ d2, int* __restrict__ knn)
{
    int warp = threadIdx.x >> 5;
    int lane = threadIdx.x & 31;
    int row = blockIdx.x * 8 + warp;
    const float* r = d2 + (size_t)row * NPTS;

    float vals[11];
    int   idxs[11];
#pragma unroll
    for (int p = 0; p < 11; ++p) { vals[p] = 3.4e38f; idxs[p] = 0x7fffffff; }

    for (int j = lane; j < NPTS; j += 32) {
        if (j == row) continue;
        float v = r[j];
        if (lessp(v, j, vals[10], idxs[10])) {
            vals[10] = v; idxs[10] = j;
#pragma unroll
            for (int p = 10; p > 0; --p) {
                if (lessp(vals[p], idxs[p], vals[p - 1], idxs[p - 1])) {
                    float tv = vals[p]; vals[p] = vals[p - 1]; vals[p - 1] = tv;
                    int ti = idxs[p]; idxs[p] = idxs[p - 1]; idxs[p - 1] = ti;
                }
            }
        }
    }

    // Merge 32 sorted lists: 10 extraction rounds via warp argmin
    for (int rr = 0; rr < 10; ++rr) {
        float bv = vals[0]; int bi = idxs[0];
        float mv = bv; int mi = bi;
#pragma unroll
        for (int off = 16; off > 0; off >>= 1) {
            float ov = __shfl_xor_sync(0xffffffffu, mv, off);
            int   oi = __shfl_xor_sync(0xffffffffu, mi, off);
            if (lessp(ov, oi, mv, mi)) { mv = ov; mi = oi; }
        }
        if (mi == bi) {  // this lane won (indices unique across lanes)
#pragma unroll
            for (int p = 0; p < 10; ++p) { vals[p] = vals[p + 1]; idxs[p] = idxs[p + 1]; }
            vals[10] = 3.4e38f; idxs[10] = 0x7fffffff;
        }
        if (lane == 0) knn[row * KNNK + rr] = mi;
    }
}

// ---------------------------------------------------------------------------
// Degree / CSR construction
// ---------------------------------------------------------------------------
__global__ void zero_cnt_kernel()
{
    int v = blockIdx.x * 256 + threadIdx.x;
    if (v < NPTS) g_cnt[v] = 0;
}

__global__ void count_kernel()
{
    int e = blockIdx.x * 256 + threadIdx.x;
    if (e < NEDGE) atomicAdd(&g_cnt[g_knn[e]], 1);
}

__global__ void dinv_kernel()
{
    int v = blockIdx.x * 256 + threadIdx.x;
    if (v < NPTS) {
        g_dinv[v] = rsqrtf((float)(g_cnt[v] + 1));  // deg = incoming + self loop
        g_fill[v] = 0;
    }
}

__global__ __launch_bounds__(1024)
void scan_kernel()
{
    __shared__ int part[1024];
    int tid = threadIdx.x;
    int base = tid * 8;
    int loc[8];
    int s = 0;
#pragma unroll
    for (int j = 0; j < 8; ++j) { loc[j] = s; s += g_cnt[base + j]; }
    part[tid] = s;
    __syncthreads();
    if (tid == 0) {
        int run = 0;
        for (int i = 0; i < 1024; ++i) { int t = part[i]; part[i] = run; run += t; }
        g_off[NPTS] = run;
    }
    __syncthreads();
    int p = part[tid];
#pragma unroll
    for (int j = 0; j < 8; ++j) g_off[base + j] = p + loc[j];
}

__global__ void fill_kernel()
{
    int e = blockIdx.x * 256 + threadIdx.x;
    if (e < NEDGE) {
        int src = e / KNNK;
        int dst = g_knn[e];
        int pos = atomicAdd(&g_fill[dst], 1);
        g_csr[g_off[dst] + pos] = src;
    }
}

// ---------------------------------------------------------------------------
// GCN aggregation (symmetric norm, self loop) + bias + BN(eval) [+ ReLU]
// One block per node; CSR gather of incoming sources.
// ---------------------------------------------------------------------------
template<int F, int TPB, bool RELU>
__global__ __launch_bounds__(TPB)
void agg_kernel(const float* __restrict__ h, float* __restrict__ out,
                const float* __restrict__ b, const float* __restrict__ g,
                const float* __restrict__ be)
{
    int v = blockIdx.x;
    float dv = g_dinv[v];
    int s = g_off[v], e = g_off[v + 1];

    const int PF = F / TPB;
    float acc[PF];
#pragma unroll
    for (int j = 0; j < PF; ++j) {
        int c = threadIdx.x + j * TPB;
        acc[j] = dv * dv * h[(size_t)v * F + c];
    }
    for (int i = s; i < e; ++i) {
        int u = g_csr[i];
        float w = g_dinv[u] * dv;
#pragma unroll
        for (int j = 0; j < PF; ++j) {
            int c = threadIdx.x + j * TPB;
            acc[j] += w * h[(size_t)u * F + c];
        }
    }
    const float invb = rsqrtf(1.0f + 1e-5f);  // BN eval: running var=1
#pragma unroll
    for (int j = 0; j < PF; ++j) {
        int c = threadIdx.x + j * TPB;
        float y = (acc[j] + b[c]) * (g[c] * invb) + be[c];
        if (RELU) y = fmaxf(y, 0.0f);
        out[(size_t)v * F + c] = y;
    }
}

// ---------------------------------------------------------------------------
// Launcher
// ---------------------------------------------------------------------------
extern "C" void kernel_launch(void* const* d_in, const int* in_sizes, int n_in,
                              void* d_out, int out_size)
{
    (void)in_sizes; (void)n_in; (void)out_size;

    const float* feat = (const float*)d_in[0];
    const float* W1   = (const float*)d_in[1];
    const float* b1   = (const float*)d_in[2];
    const float* W2   = (const float*)d_in[3];
    const float* b2   = (const float*)d_in[4];
    const float* W3   = (const float*)d_in[5];
    const float* b3   = (const float*)d_in[6];
    const float* g1   = (const float*)d_in[7];
    const float* be1  = (const float*)d_in[8];
    const float* g2   = (const float*)d_in[9];
    const float* be2  = (const float*)d_in[10];
    const float* g3   = (const float*)d_in[11];
    const float* be3  = (const float*)d_in[12];
    const float* S1w  = (const float*)d_in[13];
    const float* S1b  = (const float*)d_in[14];
    const float* S2w  = (const float*)d_in[15];
    const float* S2b  = (const float*)d_in[16];
    const float* S3w  = (const float*)d_in[17];
    const float* S3b  = (const float*)d_in[18];
    float* out = (float*)d_out;

    float *f, *sq, *d2, *h, *a, *x, *x2, *h3, *a3;
    int *knn;
    cudaGetSymbolAddress((void**)&f,   g_f);
    cudaGetSymbolAddress((void**)&sq,  g_sq);
    cudaGetSymbolAddress((void**)&d2,  g_d2);
    cudaGetSymbolAddress((void**)&knn, g_knn);
    cudaGetSymbolAddress((void**)&h,   g_h);
    cudaGetSymbolAddress((void**)&a,   g_a);
    cudaGetSymbolAddress((void**)&x,   g_x);
    cudaGetSymbolAddress((void**)&x2,  g_x2);
    cudaGetSymbolAddress((void**)&h3,  g_h3);
    cudaGetSymbolAddress((void**)&a3,  g_a3);

    // 1) f = l2norm(features); sq = rowwise |f|^2
    normalize_kernel<<<NPTS, 256>>>(feat, f, sq, DDIM);

    // 2) d2 = sq_i + sq_j - 2 f f^T
    gemm_kernel<2, true><<<dim3(NPTS / BN, NPTS / BM), 256>>>(
        f, f, d2, NPTS, NPTS, DDIM, nullptr, nullptr, sq);

    // 3) 10-NN per row (excluding self)
    topk_kernel<<<NPTS / 8, 256>>>(d2, knn);

    // 4) degrees + CSR of incoming edges
    zero_cnt_kernel<<<(NPTS + 255) / 256, 256>>>();
    count_kernel<<<(NEDGE + 255) / 256, 256>>>();
    dinv_kernel<<<(NPTS + 255) / 256, 256>>>();
    scan_kernel<<<1, 1024>>>();
    fill_kernel<<<(NEDGE + 255) / 256, 256>>>();

    // Layer 1
    gemm_kernel<0, false><<<dim3(HDIM / BN, NPTS / BM), 256>>>(
        f, W1, h, NPTS, HDIM, DDIM, nullptr, nullptr, nullptr);
    agg_kernel<HDIM, 256, true><<<NPTS, 256>>>(h, a, b1, g1, be1);
    gemm_kernel<1, false><<<dim3(DDIM / BN, NPTS / BM), 256>>>(
        a, S1w, x, NPTS, DDIM, HDIM, S1b, f, nullptr);

    // Layer 2
    gemm_kernel<0, false><<<dim3(HDIM / BN, NPTS / BM), 256>>>(
        x, W2, h, NPTS, HDIM, HDIM, nullptr, nullptr, nullptr);
    agg_kernel<HDIM, 256, true><<<NPTS, 256>>>(h, a, b2, g2, be2);
    gemm_kernel<1, false><<<dim3(DDIM / BN, NPTS / BM), 256>>>(
        a, S2w, x2, NPTS, DDIM, HDIM, S2b, f, nullptr);

    // Layer 3
    gemm_kernel<0, false><<<dim3(ODIM / BN, NPTS / BM), 256>>>(
        x2, W3, h3, NPTS, ODIM, HDIM, nullptr, nullptr, nullptr);
    agg_kernel<ODIM, 128, false><<<NPTS, 128>>>(h3, a3, b3, g3, be3);
    gemm_kernel<1, false><<<dim3(DDIM / BN, NPTS / BM), 256>>>(
        a3, S3w, x, NPTS, DDIM, ODIM, S3b, f, nullptr);

    // Output: l2norm(x3) -> d_out  (sq reused as scratch; recomputed each call)
    normalize_kernel<<<NPTS, 256>>>(x, out, nullptr, DDIM);
}